// round 1
// baseline (speedup 1.0000x reference)
#include <cuda_runtime.h>

// CrossAttention: B=8, SQ=SK=2048, DIM=1024, fp32.
// Pipeline: Q/K/V projections (NT gemm + bias) -> scores (batched NT gemm, alpha=1/32)
//           -> row softmax -> PV (batched NN gemm).

#define DIMc 1024
#define NB   8
#define SQc  2048
#define SKc  2048

// Scratch (allocation-free rule: __device__ globals)
__device__ float g_Q[(size_t)NB * SQc * DIMc];   // 64 MB
__device__ float g_K[(size_t)NB * SKc * DIMc];   // 64 MB
__device__ float g_V[(size_t)NB * SKc * DIMc];   // 64 MB
__device__ float g_S[(size_t)NB * SQc * SKc];    // 128 MB

constexpr int BM = 128, BN = 128, BK = 8, TM = 8, TN = 8;

// C[M,N] = alpha * A[M,K] @ op(B) + bias
//   BT=true : B is [N,K] row-major (NT gemm, both operands K-contiguous)
//   BT=false: B is [K,N] row-major (NN gemm)
// blockIdx.z batches via sA/sB/sC element strides.
// Requires M%BM==0, N%BN==0, K%BK==0 (true for all shapes here).
template <bool BT>
__global__ __launch_bounds__(256) void gemm_tile(
    const float* __restrict__ A, const float* __restrict__ Bm,
    const float* __restrict__ bias, float* __restrict__ C,
    int M, int N, int K, float alpha,
    long long sA, long long sB, long long sC)
{
    A  += (long long)blockIdx.z * sA;
    Bm += (long long)blockIdx.z * sB;
    C  += (long long)blockIdx.z * sC;

    __shared__ float As[BK][BM];
    __shared__ float Bs[BK][BN];

    const int tx = threadIdx.x, ty = threadIdx.y;   // 16 x 16
    const int tid = ty * 16 + tx;
    const long long bm = (long long)blockIdx.y * BM;
    const long long bn = (long long)blockIdx.x * BN;

    // A-tile load mapping: 128 rows x 8 k = 256 float4, one per thread
    const int arow = tid >> 1;
    const int acol = (tid & 1) * 4;
    const float* Ap = A + (bm + arow) * K + acol;

    // B-tile load mapping
    const float* Bp;
    int bkr = 0, bnc = 0;
    if (BT) {
        Bp = Bm + (bn + arow) * K + acol;          // [N,K]: same pattern as A
    } else {
        bkr = tid >> 5;                             // 0..7 (k)
        bnc = (tid & 31) * 4;                       // 0..124 (n)
        Bp = Bm + (long long)bkr * N + bn + bnc;    // [K,N]: contiguous along N
    }

    float acc[TM][TN] = {};

    for (int k0 = 0; k0 < K; k0 += BK) {
        float4 av = *(const float4*)(Ap + k0);
        As[acol + 0][arow] = av.x;
        As[acol + 1][arow] = av.y;
        As[acol + 2][arow] = av.z;
        As[acol + 3][arow] = av.w;
        if (BT) {
            float4 bv = *(const float4*)(Bp + k0);
            Bs[acol + 0][arow] = bv.x;
            Bs[acol + 1][arow] = bv.y;
            Bs[acol + 2][arow] = bv.z;
            Bs[acol + 3][arow] = bv.w;
        } else {
            float4 bv = *(const float4*)(Bp + (long long)k0 * N);
            *(float4*)&Bs[bkr][bnc] = bv;
        }
        __syncthreads();

        #pragma unroll
        for (int k = 0; k < BK; k++) {
            float a[TM], b[TN];
            *(float4*)&a[0] = *(const float4*)&As[k][ty * TM];
            *(float4*)&a[4] = *(const float4*)&As[k][ty * TM + 4];
            *(float4*)&b[0] = *(const float4*)&Bs[k][tx * TN];
            *(float4*)&b[4] = *(const float4*)&Bs[k][tx * TN + 4];
            #pragma unroll
            for (int i = 0; i < TM; i++)
                #pragma unroll
                for (int j = 0; j < TN; j++)
                    acc[i][j] += a[i] * b[j];
        }
        __syncthreads();
    }

    #pragma unroll
    for (int i = 0; i < TM; i++) {
        long long row = bm + ty * TM + i;
        #pragma unroll
        for (int j = 0; j < TN; j += 4) {
            long long col = bn + tx * TN + j;
            float4 o;
            o.x = acc[i][j + 0] * alpha;
            o.y = acc[i][j + 1] * alpha;
            o.z = acc[i][j + 2] * alpha;
            o.w = acc[i][j + 3] * alpha;
            if (bias) {
                float4 bb = *(const float4*)(bias + col);
                o.x += bb.x; o.y += bb.y; o.z += bb.z; o.w += bb.w;
            }
            *(float4*)&C[row * N + col] = o;
        }
    }
}

// Row softmax over SK=2048 columns; one block (256 threads) per row,
// 8 elements per thread, stride-256 coalesced.
__global__ __launch_bounds__(256) void softmax_rows(float* __restrict__ S)
{
    long long row = blockIdx.x;
    float* p = S + row * (long long)SKc;
    const int t = threadIdx.x;

    float v[8];
    float mx = -3.402823466e38f;
    #pragma unroll
    for (int i = 0; i < 8; i++) {
        v[i] = p[t + i * 256];
        mx = fmaxf(mx, v[i]);
    }

    __shared__ float shm[8];
    __shared__ float shs[8];

    #pragma unroll
    for (int o = 16; o > 0; o >>= 1)
        mx = fmaxf(mx, __shfl_xor_sync(0xffffffffu, mx, o));
    if ((t & 31) == 0) shm[t >> 5] = mx;
    __syncthreads();
    mx = shm[0];
    #pragma unroll
    for (int w = 1; w < 8; w++) mx = fmaxf(mx, shm[w]);

    float sum = 0.f;
    #pragma unroll
    for (int i = 0; i < 8; i++) {
        v[i] = expf(v[i] - mx);
        sum += v[i];
    }
    #pragma unroll
    for (int o = 16; o > 0; o >>= 1)
        sum += __shfl_xor_sync(0xffffffffu, sum, o);
    if ((t & 31) == 0) shs[t >> 5] = sum;
    __syncthreads();
    float tot = 0.f;
    #pragma unroll
    for (int w = 0; w < 8; w++) tot += shs[w];

    float inv = 1.0f / tot;
    #pragma unroll
    for (int i = 0; i < 8; i++) p[t + i * 256] = v[i] * inv;
}

extern "C" void kernel_launch(void* const* d_in, const int* in_sizes, int n_in,
                              void* d_out, int out_size)
{
    const float* x   = (const float*)d_in[0];
    const float* ctx = (const float*)d_in[1];
    const float* Wq  = (const float*)d_in[2];
    const float* bq  = (const float*)d_in[3];
    const float* Wk  = (const float*)d_in[4];
    const float* bk  = (const float*)d_in[5];
    const float* Wv  = (const float*)d_in[6];
    const float* bv  = (const float*)d_in[7];
    float* out = (float*)d_out;

    float *Q, *Kp, *V, *S;
    cudaGetSymbolAddress((void**)&Q,  g_Q);
    cudaGetSymbolAddress((void**)&Kp, g_K);
    cudaGetSymbolAddress((void**)&V,  g_V);
    cudaGetSymbolAddress((void**)&S,  g_S);

    dim3 blk(16, 16);
    const float scale = 0.03125f;  // 1/sqrt(1024)

    // Projections: [16384,1024] = [16384,1024] @ [1024,1024]^T + b
    gemm_tile<true><<<dim3(DIMc / BN, (NB * SQc) / BM, 1), blk>>>(
        x, Wq, bq, Q, NB * SQc, DIMc, DIMc, 1.f, 0, 0, 0);
    gemm_tile<true><<<dim3(DIMc / BN, (NB * SKc) / BM, 1), blk>>>(
        ctx, Wk, bk, Kp, NB * SKc, DIMc, DIMc, 1.f, 0, 0, 0);
    gemm_tile<true><<<dim3(DIMc / BN, (NB * SKc) / BM, 1), blk>>>(
        ctx, Wv, bv, V, NB * SKc, DIMc, DIMc, 1.f, 0, 0, 0);

    // Scores: per batch S[2048,2048] = scale * Q @ K^T
    gemm_tile<true><<<dim3(SKc / BN, SQc / BM, NB), blk>>>(
        Q, Kp, nullptr, S, SQc, SKc, DIMc, scale,
        (long long)SQc * DIMc, (long long)SKc * DIMc, (long long)SQc * SKc);

    // Softmax over last dim
    softmax_rows<<<NB * SQc, 256>>>(S);

    // PV: per batch O[2048,1024] = P @ V
    gemm_tile<false><<<dim3(DIMc / BN, SQc / BM, NB), blk>>>(
        S, V, nullptr, out, SQc, DIMc, SKc, 1.f,
        (long long)SQc * SKc, (long long)SKc * DIMc, (long long)SQc * DIMc);
}

// round 3
// speedup vs baseline: 2.4735x; 2.4735x over previous
#include <cuda_runtime.h>
#include <cuda_bf16.h>
#include <cstdint>

// CrossAttention B=8, SQ=SK=2048, DIM=1024, fp32 in/out.
// All GEMMs: mma.sync m16n8k16 bf16->fp32, 2-way bf16 split (3 passes).
// Pipeline: split(x,ctx,W*) -> Q,K (proj, split-out) -> Vt = Wv@ctx^T (split-out)
//           -> S = QK^T/32 (fp32) -> softmax (split-out P) -> O = P@Vt^T (fp32)

#define DIMc 1024
#define NB   8
#define SQc  2048
#define SKc  2048

#define NXQ ((size_t)NB * SQc * DIMc)   // 16M
#define NS  ((size_t)NB * SQc * SKc)    // 33.5M

__device__ __align__(128) __nv_bfloat16 g_xh[NXQ],  g_xl[NXQ];
__device__ __align__(128) __nv_bfloat16 g_ch[NXQ],  g_cl[NXQ];
__device__ __align__(128) __nv_bfloat16 g_Wqh[DIMc*DIMc], g_Wql[DIMc*DIMc];
__device__ __align__(128) __nv_bfloat16 g_Wkh[DIMc*DIMc], g_Wkl[DIMc*DIMc];
__device__ __align__(128) __nv_bfloat16 g_Wvh[DIMc*DIMc], g_Wvl[DIMc*DIMc];
__device__ __align__(128) __nv_bfloat16 g_Qh[NXQ],  g_Ql[NXQ];
__device__ __align__(128) __nv_bfloat16 g_Kh[NXQ],  g_Kl[NXQ];
__device__ __align__(128) __nv_bfloat16 g_Vth[NXQ], g_Vtl[NXQ];
__device__ __align__(128) float         g_S[NS];
__device__ __align__(128) __nv_bfloat16 g_Ph[NS],   g_Pl[NS];

// ---------------- helpers ----------------
__device__ __forceinline__ uint32_t smem_u32(const void* p) {
    uint32_t a;
    asm("{ .reg .u64 t; cvta.to.shared.u64 t, %1; cvt.u32.u64 %0, t; }"
        : "=r"(a) : "l"(p));
    return a;
}
// pack: low half = bf16(lo), high half = bf16(hi)
__device__ __forceinline__ uint32_t cvt2(float lo, float hi) {
    uint32_t r;
    asm("cvt.rn.bf16x2.f32 %0, %1, %2;" : "=r"(r) : "f"(hi), "f"(lo));
    return r;
}
__device__ __forceinline__ void cp16(uint32_t dst, const void* src) {
    asm volatile("cp.async.cg.shared.global [%0], [%1], 16;"
                 :: "r"(dst), "l"(src));
}
__device__ __forceinline__ void ldsm4(uint32_t* r, uint32_t a) {
    asm volatile("ldmatrix.sync.aligned.m8n8.x4.shared.b16 {%0,%1,%2,%3}, [%4];"
                 : "=r"(r[0]), "=r"(r[1]), "=r"(r[2]), "=r"(r[3]) : "r"(a));
}
__device__ __forceinline__ void mma16816(float* d, const uint32_t* a,
                                         const uint32_t* b) {
    asm volatile(
        "mma.sync.aligned.m16n8k16.row.col.f32.bf16.bf16.f32 "
        "{%0,%1,%2,%3}, {%4,%5,%6,%7}, {%8,%9}, {%0,%1,%2,%3};"
        : "+f"(d[0]), "+f"(d[1]), "+f"(d[2]), "+f"(d[3])
        : "r"(a[0]), "r"(a[1]), "r"(a[2]), "r"(a[3]), "r"(b[0]), "r"(b[1]));
}

constexpr int STAGES  = 4;
constexpr int TSTRIDE = 40;                       // padded bf16 elems per row
constexpr int TILE_B  = 128 * TSTRIDE * 2;        // 10240 B per tile
constexpr int STG_B   = 4 * TILE_B;               // 40960 B per stage
constexpr int SMEM_B  = STAGES * STG_B;           // 163840 B

// ---------------- GEMM: C[M,N] = alpha * A[M,K] @ B[N,K]^T (+bias) ----------------
// OSPLIT=0: fp32 C out. OSPLIT=1: split bf16 out (Chi, Clo).
// bias_mode: 0 none, 1 per-column, 2 per-row.
template <int OSPLIT>
__global__ __launch_bounds__(256, 1)
void gemm_mma(const __nv_bfloat16* __restrict__ Ah, const __nv_bfloat16* __restrict__ Al,
              const __nv_bfloat16* __restrict__ Bh, const __nv_bfloat16* __restrict__ Bl,
              const float* __restrict__ bias, int bias_mode,
              float* __restrict__ C,
              __nv_bfloat16* __restrict__ Chi, __nv_bfloat16* __restrict__ Clo,
              int M, int N, int K, float alpha,
              long long sA, long long sB, long long sC)
{
    extern __shared__ __align__(1024) char smem[];
    const uint32_t tb = smem_u32(smem);

    const int tid  = threadIdx.x;
    const int lane = tid & 31;
    const int wid  = tid >> 5;
    const int wm   = wid & 3;        // 4 warps along M (32 rows each)
    const int wn   = wid >> 2;       // 2 warps along N (64 cols each)

    const long long bm = (long long)blockIdx.y * 128;
    const long long bn = (long long)blockIdx.x * 128;
    Ah += (long long)blockIdx.z * sA + bm * K;
    Al += (long long)blockIdx.z * sA + bm * K;
    Bh += (long long)blockIdx.z * sB + bn * K;
    Bl += (long long)blockIdx.z * sB + bn * K;

    const int ktot = K >> 5;

    // cp.async tile loader: 512 chunks of 16B per array, 2 per thread
    auto load_tile = [&](int kt) {
        const int k0 = kt << 5;
        const uint32_t sbase = tb + (uint32_t)(kt % STAGES) * STG_B;
        #pragma unroll
        for (int rep = 0; rep < 2; ++rep) {
            const int ch  = tid + rep * 256;
            const int row = ch >> 2;
            const int c   = ch & 3;
            const size_t g = (size_t)row * K + k0 + c * 8;
            const uint32_t s = sbase + (uint32_t)(row * TSTRIDE + c * 8) * 2;
            cp16(s,              Ah + g);
            cp16(s + TILE_B,     Al + g);
            cp16(s + 2 * TILE_B, Bh + g);
            cp16(s + 3 * TILE_B, Bl + g);
        }
    };

    // ldmatrix per-lane offsets
    const int a_r = (lane & 7) + ((lane >> 3) & 1) * 8;  // row within 16
    const int a_k = (lane >> 4) * 8;                     // 0 / 8
    const int b_n = (lane & 7) + ((lane >> 4) & 1) * 8;  // row within 16 (n)
    const int b_k = ((lane >> 3) & 1) * 8;               // 0 / 8

    float acc[2][8][4] = {};

    #pragma unroll
    for (int s = 0; s < STAGES - 1; ++s) {
        load_tile(s);
        asm volatile("cp.async.commit_group;" ::: "memory");
    }

    #pragma unroll 1
    for (int kt = 0; kt < ktot; ++kt) {
        asm volatile("cp.async.wait_group %0;" :: "n"(STAGES - 2) : "memory");
        __syncthreads();

        const uint32_t sA0 = tb + (uint32_t)(kt % STAGES) * STG_B;
        #pragma unroll
        for (int k16 = 0; k16 < 2; ++k16) {
            uint32_t aH[2][4], aL[2][4], bH[4][4], bL[4][4];
            #pragma unroll
            for (int mt = 0; mt < 2; ++mt) {
                const uint32_t off =
                    (uint32_t)((wm * 32 + mt * 16 + a_r) * TSTRIDE + k16 * 16 + a_k) * 2;
                ldsm4(aH[mt], sA0 + off);
                ldsm4(aL[mt], sA0 + TILE_B + off);
            }
            #pragma unroll
            for (int j = 0; j < 4; ++j) {
                const uint32_t off =
                    (uint32_t)((wn * 64 + j * 16 + b_n) * TSTRIDE + k16 * 16 + b_k) * 2;
                ldsm4(bH[j], sA0 + 2 * TILE_B + off);
                ldsm4(bL[j], sA0 + 3 * TILE_B + off);
            }
            #pragma unroll
            for (int mt = 0; mt < 2; ++mt) {
                #pragma unroll
                for (int j = 0; j < 4; ++j) {
                    mma16816(acc[mt][2 * j],     aH[mt], bH[j]);      // hi*hi
                    mma16816(acc[mt][2 * j + 1], aH[mt], bH[j] + 2);
                    mma16816(acc[mt][2 * j],     aH[mt], bL[j]);      // hi*lo
                    mma16816(acc[mt][2 * j + 1], aH[mt], bL[j] + 2);
                    mma16816(acc[mt][2 * j],     aL[mt], bH[j]);      // lo*hi
                    mma16816(acc[mt][2 * j + 1], aL[mt], bH[j] + 2);
                }
            }
        }
        __syncthreads();
        if (kt + STAGES - 1 < ktot) load_tile(kt + STAGES - 1);
        asm volatile("cp.async.commit_group;" ::: "memory");
    }

    // epilogue
    const int gr = lane >> 2;
    const int c2 = (lane & 3) * 2;
    #pragma unroll
    for (int mt = 0; mt < 2; ++mt) {
        #pragma unroll
        for (int nt = 0; nt < 8; ++nt) {
            const long long m0 = bm + wm * 32 + mt * 16 + gr;
            const long long n  = bn + wn * 64 + nt * 8 + c2;
            const float* a4 = acc[mt][nt];
            float v0 = a4[0] * alpha, v1 = a4[1] * alpha;
            float v2 = a4[2] * alpha, v3 = a4[3] * alpha;
            if (bias_mode == 1) {
                const float b0 = bias[n], b1 = bias[n + 1];
                v0 += b0; v1 += b1; v2 += b0; v3 += b1;
            } else if (bias_mode == 2) {
                const float b0 = bias[m0], b1 = bias[m0 + 8];
                v0 += b0; v1 += b0; v2 += b1; v3 += b1;
            }
            if (OSPLIT == 0) {
                float* Cb = C + (long long)blockIdx.z * sC;
                *(float2*)(Cb + m0 * N + n)       = make_float2(v0, v1);
                *(float2*)(Cb + (m0 + 8) * N + n) = make_float2(v2, v3);
            } else {
                __nv_bfloat16* Hb = Chi + (long long)blockIdx.z * sC;
                __nv_bfloat16* Lb = Clo + (long long)blockIdx.z * sC;
                uint32_t hp = cvt2(v0, v1);
                float h0 = __uint_as_float(hp << 16);
                float h1 = __uint_as_float(hp & 0xFFFF0000u);
                uint32_t lp = cvt2(v0 - h0, v1 - h1);
                *(uint32_t*)(Hb + m0 * N + n) = hp;
                *(uint32_t*)(Lb + m0 * N + n) = lp;
                hp = cvt2(v2, v3);
                h0 = __uint_as_float(hp << 16);
                h1 = __uint_as_float(hp & 0xFFFF0000u);
                lp = cvt2(v2 - h0, v3 - h1);
                *(uint32_t*)(Hb + (m0 + 8) * N + n) = hp;
                *(uint32_t*)(Lb + (m0 + 8) * N + n) = lp;
            }
        }
    }
}

// ---------------- fp32 -> split bf16 ----------------
__global__ __launch_bounds__(256)
void split2(const float4* __restrict__ in, uint2* __restrict__ hi,
            uint2* __restrict__ lo, int n4)
{
    int i = blockIdx.x * 256 + threadIdx.x;
    if (i >= n4) return;
    float4 v = in[i];
    uint32_t h01 = cvt2(v.x, v.y);
    uint32_t h23 = cvt2(v.z, v.w);
    float r0 = v.x - __uint_as_float(h01 << 16);
    float r1 = v.y - __uint_as_float(h01 & 0xFFFF0000u);
    float r2 = v.z - __uint_as_float(h23 << 16);
    float r3 = v.w - __uint_as_float(h23 & 0xFFFF0000u);
    hi[i] = make_uint2(h01, h23);
    lo[i] = make_uint2(cvt2(r0, r1), cvt2(r2, r3));
}

// ---------------- softmax (fp32 in, split bf16 out) ----------------
__global__ __launch_bounds__(256)
void softmax_split(const float* __restrict__ S, __nv_bfloat16* __restrict__ Ph,
                   __nv_bfloat16* __restrict__ Pl)
{
    const long long row = blockIdx.x;
    const float* p = S + row * (long long)SKc;
    const int t = threadIdx.x;

    float v[8];
    float mx = -3.402823466e38f;
    #pragma unroll
    for (int i = 0; i < 8; i++) {
        v[i] = p[t + i * 256];
        mx = fmaxf(mx, v[i]);
    }
    __shared__ float shm[8], shs[8];
    #pragma unroll
    for (int o = 16; o > 0; o >>= 1)
        mx = fmaxf(mx, __shfl_xor_sync(0xffffffffu, mx, o));
    if ((t & 31) == 0) shm[t >> 5] = mx;
    __syncthreads();
    mx = shm[0];
    #pragma unroll
    for (int w = 1; w < 8; w++) mx = fmaxf(mx, shm[w]);

    float sum = 0.f;
    #pragma unroll
    for (int i = 0; i < 8; i++) { v[i] = expf(v[i] - mx); sum += v[i]; }
    #pragma unroll
    for (int o = 16; o > 0; o >>= 1)
        sum += __shfl_xor_sync(0xffffffffu, sum, o);
    if ((t & 31) == 0) shs[t >> 5] = sum;
    __syncthreads();
    float tot = 0.f;
    #pragma unroll
    for (int w = 0; w < 8; w++) tot += shs[w];

    const float inv = 1.0f / tot;
    __nv_bfloat16* ph = Ph + row * (long long)SKc;
    __nv_bfloat16* pl = Pl + row * (long long)SKc;
    #pragma unroll
    for (int i = 0; i < 8; i++) {
        const float pv = v[i] * inv;
        const __nv_bfloat16 h = __float2bfloat16(pv);
        ph[t + i * 256] = h;
        pl[t + i * 256] = __float2bfloat16(pv - __bfloat162float(h));
    }
}

// ---------------- launch ----------------
extern "C" void kernel_launch(void* const* d_in, const int* in_sizes, int n_in,
                              void* d_out, int out_size)
{
    const float* x   = (const float*)d_in[0];
    const float* ctx = (const float*)d_in[1];
    const float* Wq  = (const float*)d_in[2];
    const float* bq  = (const float*)d_in[3];
    const float* Wk  = (const float*)d_in[4];
    const float* bk  = (const float*)d_in[5];
    const float* Wv  = (const float*)d_in[6];
    const float* bv  = (const float*)d_in[7];
    float* out = (float*)d_out;

    __nv_bfloat16 *xh, *xl, *ch, *cl, *Wqh, *Wql, *Wkh, *Wkl, *Wvh, *Wvl;
    __nv_bfloat16 *Qh, *Ql, *Kh, *Kl, *Vth, *Vtl, *Ph, *Pl;
    float* S;
    cudaGetSymbolAddress((void**)&xh,  g_xh);  cudaGetSymbolAddress((void**)&xl,  g_xl);
    cudaGetSymbolAddress((void**)&ch,  g_ch);  cudaGetSymbolAddress((void**)&cl,  g_cl);
    cudaGetSymbolAddress((void**)&Wqh, g_Wqh); cudaGetSymbolAddress((void**)&Wql, g_Wql);
    cudaGetSymbolAddress((void**)&Wkh, g_Wkh); cudaGetSymbolAddress((void**)&Wkl, g_Wkl);
    cudaGetSymbolAddress((void**)&Wvh, g_Wvh); cudaGetSymbolAddress((void**)&Wvl, g_Wvl);
    cudaGetSymbolAddress((void**)&Qh,  g_Qh);  cudaGetSymbolAddress((void**)&Ql,  g_Ql);
    cudaGetSymbolAddress((void**)&Kh,  g_Kh);  cudaGetSymbolAddress((void**)&Kl,  g_Kl);
    cudaGetSymbolAddress((void**)&Vth, g_Vth); cudaGetSymbolAddress((void**)&Vtl, g_Vtl);
    cudaGetSymbolAddress((void**)&Ph,  g_Ph);  cudaGetSymbolAddress((void**)&Pl,  g_Pl);
    cudaGetSymbolAddress((void**)&S,   g_S);

    cudaFuncSetAttribute(gemm_mma<0>, cudaFuncAttributeMaxDynamicSharedMemorySize, SMEM_B);
    cudaFuncSetAttribute(gemm_mma<1>, cudaFuncAttributeMaxDynamicSharedMemorySize, SMEM_B);

    // split inputs
    const int n4x = (int)(NXQ / 4), n4w = DIMc * DIMc / 4;
    split2<<<(n4x + 255) / 256, 256>>>((const float4*)x,   (uint2*)xh,  (uint2*)xl,  n4x);
    split2<<<(n4x + 255) / 256, 256>>>((const float4*)ctx, (uint2*)ch,  (uint2*)cl,  n4x);
    split2<<<(n4w + 255) / 256, 256>>>((const float4*)Wq,  (uint2*)Wqh, (uint2*)Wql, n4w);
    split2<<<(n4w + 255) / 256, 256>>>((const float4*)Wk,  (uint2*)Wkh, (uint2*)Wkl, n4w);
    split2<<<(n4w + 255) / 256, 256>>>((const float4*)Wv,  (uint2*)Wvh, (uint2*)Wvl, n4w);

    const float scale = 0.03125f;   // 1/sqrt(1024)

    // Q = x @ Wq^T + bq  -> split
    gemm_mma<1><<<dim3(DIMc / 128, (NB * SQc) / 128, 1), 256, SMEM_B>>>(
        xh, xl, Wqh, Wql, bq, 1, nullptr, Qh, Ql,
        NB * SQc, DIMc, DIMc, 1.f, 0, 0, 0);
    // K = ctx @ Wk^T + bk -> split
    gemm_mma<1><<<dim3(DIMc / 128, (NB * SKc) / 128, 1), 256, SMEM_B>>>(
        ch, cl, Wkh, Wkl, bk, 1, nullptr, Kh, Kl,
        NB * SKc, DIMc, DIMc, 1.f, 0, 0, 0);
    // Vt = Wv @ ctx^T + bv(row) -> split   (per batch [1024, 2048])
    gemm_mma<1><<<dim3(SKc / 128, DIMc / 128, NB), 256, SMEM_B>>>(
        Wvh, Wvl, ch, cl, bv, 2, nullptr, Vth, Vtl,
        DIMc, SKc, DIMc, 1.f, 0, (long long)SKc * DIMc, (long long)DIMc * SKc);
    // S = (Q @ K^T)/32  (fp32)   per batch [2048, 2048]
    gemm_mma<0><<<dim3(SKc / 128, SQc / 128, NB), 256, SMEM_B>>>(
        Qh, Ql, Kh, Kl, nullptr, 0, S, nullptr, nullptr,
        SQc, SKc, DIMc, scale,
        (long long)SQc * DIMc, (long long)SKc * DIMc, (long long)SQc * SKc);
    // softmax -> split P
    softmax_split<<<NB * SQc, 256>>>(S, Ph, Pl);
    // O = P @ Vt^T (fp32)        per batch [2048, 1024]
    gemm_mma<0><<<dim3(DIMc / 128, SQc / 128, NB), 256, SMEM_B>>>(
        Ph, Pl, Vth, Vtl, nullptr, 0, out, nullptr, nullptr,
        SQc, DIMc, SKc, 1.f,
        (long long)SQc * SKc, (long long)DIMc * SKc, (long long)SQc * DIMc);
}